// round 4
// baseline (speedup 1.0000x reference)
#include <cuda_runtime.h>
#include <cstdint>

typedef unsigned long long u64;

#define MAXN   16384
#define RUN    512
#define NCELL  512           // 8x8x8 cells of 5 Angstrom
#define CAP    128           // bucket capacity per cell (expected ~32)
#define NB_CAP 2560          // smem neighborhood capacity (float4) = 40KB
#define NBLK   64
#define NTHR   512

// ---------------- scratch (device globals, zero-initialized at load) --------
__device__ float        g_mind[MAXN];
__device__ int          g_counts[MAXN];        // only far atoms' entries read
__device__ int          g_cellcnt[NCELL];      // reset in phase C each run
__device__ float4       g_bucket[NCELL * CAP];
__device__ int          g_bucketidx[NCELL * CAP];
__device__ int          g_maxcount;            // reset in merge stage 0 each run
__device__ u64          g_runsA[MAXN];
__device__ u64          g_runsB[MAXN];
__device__ unsigned int g_arrive;              // self-resetting
__device__ unsigned int g_gen;                 // monotonic across replays

__constant__ float c_bond[20] = {
    1.05f, 1.3f, 1.1f, 1.2f, 1.0f, 1.1f, 1.2f, 1.0f, 1.4f, 1.0f,
    1.0f,  1.3f, 1.0f, 1.5f, 1.0f, 1.05f, 1.05f, 1.6f, 1.4f, 1.1f
};

// ---------------- grid barrier (all NBLK blocks co-resident) -----------------
__device__ __forceinline__ void grid_bar(unsigned int& mygen) {
    __syncthreads();
    if (threadIdx.x == 0) {
        __threadfence();
        unsigned int a = atomicAdd(&g_arrive, 1u);
        if (a == NBLK - 1) {
            g_arrive = 0;
            __threadfence();
            *(volatile unsigned int*)&g_gen = mygen + 1u;
        } else {
            while (*(volatile unsigned int*)&g_gen == mygen) { }
        }
        __threadfence();
    }
    __syncthreads();
    mygen++;
}

union SmemU {
    float4 nb[NB_CAP];     // phase B neighborhood (40KB)
    u64    keys[2 * RUN];  // phase C/merge sort buffer (8KB)
    float  ligs[192];      // phase A ligand coords
};

// ---------------- merge two descending 512-runs, keep top 512 ----------------
__device__ __forceinline__ void merge2(const u64* __restrict__ src,
                                       u64* __restrict__ dst,
                                       int b, u64* s) {
    int t = threadIdx.x;
    s[t]       = src[(2 * b) * RUN + t];
    s[RUN + t] = src[(2 * b + 1) * RUN + (RUN - 1 - t)];  // reversed -> bitonic
    __syncthreads();
    for (int j = RUN; j > 0; j >>= 1) {
        int i = ((t & ~(j - 1)) << 1) | (t & (j - 1));
        int p = i | j;
        u64 a = s[i], c = s[p];
        if (a < c) { s[i] = c; s[p] = a; }
        __syncthreads();
    }
    dst[b * RUN + t] = s[t];
    __syncthreads();
}

// ---------------- the single fused kernel -------------------------------------
__global__ void __launch_bounds__(NTHR) k_fused(const float* __restrict__ pos,
                                                const float* __restrict__ lig,
                                                const float* __restrict__ x,
                                                float* __restrict__ out,
                                                int N, int M, int F, int K) {
    __shared__ SmemU sm;
    unsigned int mygen = *(volatile unsigned int*)&g_gen;
    int t = threadIdx.x;

    // ============ Phase A: min dist to ligand + bucket scatter ============
    for (int q = t; q < M * 3; q += NTHR) sm.ligs[q] = lig[q];
    __syncthreads();

    for (int i = blockIdx.x * NTHR + t; i < N; i += NBLK * NTHR) {
        float px = pos[3 * i + 0], py = pos[3 * i + 1], pz = pos[3 * i + 2];
        float best = 3.4e38f;
        for (int m = 0; m < M; m++) {
            float dx = px - sm.ligs[3 * m + 0];
            float dy = py - sm.ligs[3 * m + 1];
            float dz = pz - sm.ligs[3 * m + 2];
            best = fminf(best, dx * dx + dy * dy + dz * dz);
        }
        float d = sqrtf(fmaxf(best, 1e-12f));
        g_mind[i] = d;

        if (d > 8.0f) {
            int cx = min((int)(px * 0.2f), 7);
            int cy = min((int)(py * 0.2f), 7);
            int cz = min((int)(pz * 0.2f), 7);
            int c  = (cz << 6) | (cy << 3) | cx;
            int r  = atomicAdd(&g_cellcnt[c], 1);
            if (r < CAP) {
                g_bucket[c * CAP + r]    = make_float4(px, py, pz, 0.0f);
                g_bucketidx[c * CAP + r] = i;
            }
        }
    }
    grid_bar(mygen);

    // ============ Phase B: per-cell neighbor counts ============
    {
        int warp = t >> 5, lane = t & 31;
        for (int c = blockIdx.x; c < NCELL; c += NBLK) {
            int A = min(g_cellcnt[c], CAP);
            int cx = c & 7, cy = (c >> 3) & 7, cz = c >> 6;

            int T = 0, T0 = 0;
            for (int dz = -1; dz <= 1; dz++) {
                int z = cz + dz; if (z < 0 || z > 7) continue;
                for (int dy = -1; dy <= 1; dy++) {
                    int y = cy + dy; if (y < 0 || y > 7) continue;
                    for (int dx = -1; dx <= 1; dx++) {
                        int xx = cx + dx; if (xx < 0 || xx > 7) continue;
                        int nc  = (z << 6) | (y << 3) | xx;
                        int len = min(g_cellcnt[nc], CAP);
                        if (T + len > NB_CAP) len = NB_CAP - T;
                        if (nc == c) T0 = T;
                        for (int k = t; k < len; k += NTHR)
                            sm.nb[T + k] = g_bucket[nc * CAP + k];
                        T += len;
                    }
                }
            }
            __syncthreads();

            int wmax = 0;
            for (int a = warp; a < A; a += (NTHR >> 5)) {
                float4 p = sm.nb[T0 + a];
                int cnt = 0;
                for (int j = lane; j < T; j += 32) {
                    float4 q = sm.nb[j];
                    float dx = p.x - q.x, dy = p.y - q.y, dz = p.z - q.z;
                    float d2 = dx * dx + dy * dy + dz * dz;
                    cnt += (d2 < 25.0f && d2 > 0.0f) ? 1 : 0;
                }
                #pragma unroll
                for (int o = 16; o > 0; o >>= 1)
                    cnt += __shfl_down_sync(0xffffffffu, cnt, o);
                if (lane == 0) {
                    g_counts[g_bucketidx[c * CAP + a]] = cnt;
                    wmax = max(wmax, cnt);
                }
            }
            if (lane == 0 && wmax > 0) atomicMax(&g_maxcount, wmax);
            __syncthreads();   // protect sm.nb before next cell's gather
        }
    }
    grid_bar(mygen);

    // ============ Phase C: score + key + block bitonic sort of 512 ============
    int runs = (N + RUN - 1) / RUN;   // 32
    if ((int)blockIdx.x < runs) {
        int i = blockIdx.x * RUN + t;
        u64 key = 0ULL;
        if (i < N) {
            float d = g_mind[i];
            float sc;
            if (d <= 3.5f) {
                sc = 10.0f;
            } else if (d <= 8.0f) {
                sc = 5.0f * (8.0f - d) / 8.0f;
            } else {
                float mx = (float)g_maxcount;
                mx = (mx > 0.0f) ? mx : 1.0f;
                sc = 1.0f - (float)g_counts[i] / (mx + 1e-6f);
            }
            int rt = (int)x[i * F + 1];
            rt = min(max(rt, 0), 19);
            sc *= c_bond[rt];

            out[i] = sc;

            unsigned int b = __float_as_uint(sc);
            unsigned int u = b ^ ((b >> 31) ? 0xFFFFFFFFu : 0x80000000u);
            key = ((u64)u << 32) | (u64)(0xFFFFFFFFu - (unsigned)i);
        }
        sm.keys[t] = key;
        __syncthreads();

        for (int k = 2; k <= RUN; k <<= 1) {
            for (int j = k >> 1; j > 0; j >>= 1) {
                int ixj = t ^ j;
                if (ixj > t) {
                    u64 a = sm.keys[t], c = sm.keys[ixj];
                    bool descRegion = ((t & k) == 0);
                    if (descRegion ? (a < c) : (a > c)) { sm.keys[t] = c; sm.keys[ixj] = a; }
                }
                __syncthreads();
            }
        }
        g_runsA[blockIdx.x * RUN + t] = sm.keys[t];
    }
    if (blockIdx.x == (unsigned)runs && t < NCELL) g_cellcnt[t] = 0;  // self-clean
    grid_bar(mygen);

    // ============ Merge tree: 32 -> 16 -> 8 -> 4 -> 2 (grid-barriered) ========
    int srcA = 1;
    bool first = true;
    while (runs > 2) {
        int nb2 = runs >> 1;
        if ((int)blockIdx.x < nb2)
            merge2(srcA ? g_runsA : g_runsB, srcA ? g_runsB : g_runsA,
                   blockIdx.x, sm.keys);
        if (first && blockIdx.x == (unsigned)nb2 && t == 0) g_maxcount = 0;  // self-clean
        first = false;
        grid_bar(mygen);
        srcA ^= 1;
        runs = nb2;
    }

    // ============ Final merge of 2 runs + unpack/write top-K (block 0) ========
    if (blockIdx.x == 0) {
        const u64* src = srcA ? g_runsA : g_runsB;
        sm.keys[t]       = src[t];
        sm.keys[RUN + t] = src[RUN + (RUN - 1 - t)];
        __syncthreads();

        for (int j = RUN; j > 0; j >>= 1) {
            int i = ((t & ~(j - 1)) << 1) | (t & (j - 1));
            int p = i | j;
            u64 a = sm.keys[i], c = sm.keys[p];
            if (a < c) { sm.keys[i] = c; sm.keys[p] = a; }
            __syncthreads();
        }

        if (t < K) {
            u64 key = sm.keys[t];
            unsigned int u = (unsigned int)(key >> 32);
            unsigned int b = (u >> 31) ? (u ^ 0x80000000u) : (~u);
            float sc = __uint_as_float(b);
            unsigned int idx = 0xFFFFFFFFu - (unsigned int)(key & 0xFFFFFFFFull);
            out[N + t]     = sc;
            out[N + K + t] = (float)idx;
        }
    }
}

// ---------------- launch ------------------------------------------------------
extern "C" void kernel_launch(void* const* d_in, const int* in_sizes, int n_in,
                              void* d_out, int out_size) {
    const float* pos = (const float*)d_in[0];
    const float* lig = (const float*)d_in[1];
    const float* x   = (const float*)d_in[2];
    int N = in_sizes[0] / 3;          // 16384
    int M = in_sizes[1] / 3;          // 64
    int F = in_sizes[2] / N;          // 16
    int K = (out_size - N) / 2;       // 512
    float* out = (float*)d_out;

    k_fused<<<NBLK, NTHR>>>(pos, lig, x, out, N, M, F, K);
}

// round 5
// speedup vs baseline: 1.8196x; 1.8196x over previous
#include <cuda_runtime.h>
#include <cstdint>

typedef unsigned long long u64;

#define MAXN   16384
#define NCELL  512           // 8x8x8 cells of 5 Angstrom
#define CAP    128           // bucket capacity per cell (expected ~32)
#define NB_CAP 2560          // smem neighborhood capacity (float4) = 40KB
#define NBIN   4096          // histogram bins = top 12 bits of ordered key
#define CAND   2048          // candidate buffer for final sort

// ---------------- scratch (device globals, zero-initialized at load) --------
__device__ float  g_mind[MAXN];
__device__ int    g_counts[MAXN];          // only far atoms' entries read
__device__ int    g_cellcnt[NCELL];        // reset in k_scorehist each run
__device__ float4 g_bucket[NCELL * CAP];
__device__ int    g_bucketidx[NCELL * CAP];
__device__ int    g_maxcount;              // reset in k_selectsort each run
__device__ u64    g_keys[MAXN];
__device__ int    g_hist[NBIN];            // reset in k_selectsort each run

__constant__ float c_bond[20] = {
    1.05f, 1.3f, 1.1f, 1.2f, 1.0f, 1.1f, 1.2f, 1.0f, 1.4f, 1.0f,
    1.0f,  1.3f, 1.0f, 1.5f, 1.0f, 1.05f, 1.05f, 1.6f, 1.4f, 1.1f
};

// ---------------- k1: min dist to ligand + direct bucket scatter -------------
__global__ void k_mind(const float* __restrict__ pos,
                       const float* __restrict__ lig,
                       int N, int M) {
    __shared__ float s_lig[3 * 256];
    for (int t = threadIdx.x; t < M * 3; t += blockDim.x) s_lig[t] = lig[t];
    __syncthreads();

    int i = blockIdx.x * blockDim.x + threadIdx.x;
    if (i >= N) return;

    float px = pos[3 * i + 0], py = pos[3 * i + 1], pz = pos[3 * i + 2];
    float best = 3.4e38f;
    for (int m = 0; m < M; m++) {
        float dx = px - s_lig[3 * m + 0];
        float dy = py - s_lig[3 * m + 1];
        float dz = pz - s_lig[3 * m + 2];
        best = fminf(best, dx * dx + dy * dy + dz * dz);
    }
    float d = sqrtf(fmaxf(best, 1e-12f));
    g_mind[i] = d;

    if (d > 8.0f) {
        int cx = min((int)(px * 0.2f), 7);
        int cy = min((int)(py * 0.2f), 7);
        int cz = min((int)(pz * 0.2f), 7);
        int c  = (cz << 6) | (cy << 3) | cx;
        int r  = atomicAdd(&g_cellcnt[c], 1);
        if (r < CAP) {
            g_bucket[c * CAP + r]    = make_float4(px, py, pz, 0.0f);
            g_bucketidx[c * CAP + r] = i;
        }
    }
}

// ---------------- k2: per-cell neighbor counts (27-cell smem gather) ---------
__global__ void __launch_bounds__(256) k_counts() {
    __shared__ float4 s_nb[NB_CAP];

    int c = blockIdx.x;
    int A = min(g_cellcnt[c], CAP);
    if (A == 0) return;

    int cx = c & 7, cy = (c >> 3) & 7, cz = c >> 6;

    int T = 0, T0 = 0;
    for (int dz = -1; dz <= 1; dz++) {
        int z = cz + dz; if (z < 0 || z > 7) continue;
        for (int dy = -1; dy <= 1; dy++) {
            int y = cy + dy; if (y < 0 || y > 7) continue;
            for (int dx = -1; dx <= 1; dx++) {
                int x = cx + dx; if (x < 0 || x > 7) continue;
                int nc  = (z << 6) | (y << 3) | x;
                int len = min(g_cellcnt[nc], CAP);
                if (T + len > NB_CAP) len = NB_CAP - T;  // safety clamp
                if (nc == c) T0 = T;
                for (int k = threadIdx.x; k < len; k += blockDim.x)
                    s_nb[T + k] = g_bucket[nc * CAP + k];
                T += len;
            }
        }
    }
    __syncthreads();

    int warp = threadIdx.x >> 5, lane = threadIdx.x & 31;
    int nwarps = blockDim.x >> 5;
    int wmax = 0;
    for (int a = warp; a < A; a += nwarps) {
        float4 p = s_nb[T0 + a];
        int cnt = 0;
        for (int j = lane; j < T; j += 32) {
            float4 q = s_nb[j];
            float dx = p.x - q.x, dy = p.y - q.y, dz = p.z - q.z;
            float d2 = dx * dx + dy * dy + dz * dz;
            cnt += (d2 < 25.0f && d2 > 0.0f) ? 1 : 0;
        }
        #pragma unroll
        for (int o = 16; o > 0; o >>= 1)
            cnt += __shfl_down_sync(0xffffffffu, cnt, o);
        if (lane == 0) {
            g_counts[g_bucketidx[c * CAP + a]] = cnt;
            wmax = max(wmax, cnt);
        }
    }
    if (lane == 0 && wmax > 0) atomicMax(&g_maxcount, wmax);
}

// ---------------- k3: score + key + 4096-bin histogram ------------------------
__global__ void k_scorehist(const float* __restrict__ x,
                            float* __restrict__ out, int N, int F) {
    int i = blockIdx.x * blockDim.x + threadIdx.x;

    // self-clean cell counters (k_counts already consumed them)
    if (blockIdx.x == 0) {
        for (int q = threadIdx.x; q < NCELL; q += blockDim.x) g_cellcnt[q] = 0;
    }
    if (i >= N) return;

    float d = g_mind[i];
    float sc;
    if (d <= 3.5f) {
        sc = 10.0f;
    } else if (d <= 8.0f) {
        sc = 5.0f * (8.0f - d) / 8.0f;
    } else {
        float mx = (float)g_maxcount;
        mx = (mx > 0.0f) ? mx : 1.0f;
        sc = 1.0f - (float)g_counts[i] / (mx + 1e-6f);
    }
    int rt = (int)x[i * F + 1];
    rt = min(max(rt, 0), 19);
    sc *= c_bond[rt];

    out[i] = sc;

    unsigned int b = __float_as_uint(sc);
    unsigned int u = b ^ ((b >> 31) ? 0xFFFFFFFFu : 0x80000000u);  // order-preserving
    u64 key = ((u64)u << 32) | (u64)(0xFFFFFFFFu - (unsigned)i);
    g_keys[i] = key;
    atomicAdd(&g_hist[(int)(key >> 52)], 1);
}

// ---------------- k4: threshold select + compact + sort + write (1 block) ----
__global__ void __launch_bounds__(1024) k_selectsort(float* __restrict__ out,
                                                     int N, int K) {
    __shared__ int h[NBIN];        // 16KB
    __shared__ u64 cand[CAND];     // 16KB
    __shared__ int s_thr, s_cnt;

    int t = threadIdx.x;

    // load histogram, self-clean global copy
    for (int i = t; i < NBIN; i += 1024) { h[i] = g_hist[i]; g_hist[i] = 0; }
    if (t == 0) { s_cnt = 0; s_thr = 0; g_maxcount = 0; }
    __syncthreads();

    // inclusive suffix scan over 4096 bins: h[i] = # keys with bin >= i
    for (int off = 1; off < NBIN; off <<= 1) {
        int val[4]; int q = 0;
        for (int i = t; i < NBIN; i += 1024, q++)
            val[q] = h[i] + ((i + off < NBIN) ? h[i + off] : 0);
        __syncthreads();
        q = 0;
        for (int i = t; i < NBIN; i += 1024, q++) h[i] = val[q];
        __syncthreads();
    }

    // threshold bin: largest b with suffix count >= K
    for (int i = t; i < NBIN; i += 1024) {
        int hb = h[i];
        int hn = (i + 1 < NBIN) ? h[i + 1] : 0;
        if (hb >= K && hn < K) s_thr = i;   // exactly one bin satisfies this
    }
    __syncthreads();
    int Bt = s_thr;

    // compact candidates (bin >= Bt); key uniqueness makes order irrelevant
    for (int i = t; i < N; i += 1024) {
        u64 key = g_keys[i];
        if ((int)(key >> 52) >= Bt) {
            int p = atomicAdd(&s_cnt, 1);
            if (p < CAND) cand[p] = key;
        }
    }
    __syncthreads();
    int total = min(s_cnt, CAND);
    for (int i = t; i < CAND; i += 1024)
        if (i >= total) cand[i] = 0ULL;     // pad (real keys have MSB set)
    __syncthreads();

    // bitonic full sort of 2048, descending
    for (int k = 2; k <= CAND; k <<= 1) {
        for (int j = k >> 1; j > 0; j >>= 1) {
            for (int idx = t; idx < CAND; idx += 1024) {
                int ixj = idx ^ j;
                if (ixj > idx) {
                    bool desc = ((idx & k) == 0);
                    u64 a = cand[idx], c = cand[ixj];
                    if (desc ? (a < c) : (a > c)) { cand[idx] = c; cand[ixj] = a; }
                }
            }
            __syncthreads();
        }
    }

    // write top-K scores + indices
    if (t < K) {
        u64 key = cand[t];
        unsigned int u = (unsigned int)(key >> 32);
        unsigned int b = (u >> 31) ? (u ^ 0x80000000u) : (~u);
        float sc = __uint_as_float(b);
        unsigned int idx = 0xFFFFFFFFu - (unsigned int)(key & 0xFFFFFFFFull);
        out[N + t]     = sc;
        out[N + K + t] = (float)idx;
    }
}

// ---------------- launch ------------------------------------------------------
extern "C" void kernel_launch(void* const* d_in, const int* in_sizes, int n_in,
                              void* d_out, int out_size) {
    const float* pos = (const float*)d_in[0];
    const float* lig = (const float*)d_in[1];
    const float* x   = (const float*)d_in[2];
    int N = in_sizes[0] / 3;          // 16384
    int M = in_sizes[1] / 3;          // 64
    int F = in_sizes[2] / N;          // 16
    int K = (out_size - N) / 2;       // 512
    float* out = (float*)d_out;

    k_mind<<<(N + 255) / 256, 256>>>(pos, lig, N, M);
    k_counts<<<NCELL, 256>>>();
    k_scorehist<<<(N + 255) / 256, 256>>>(x, out, N, F);
    k_selectsort<<<1, 1024>>>(out, N, K);
}

// round 6
// speedup vs baseline: 2.0359x; 1.1189x over previous
#include <cuda_runtime.h>
#include <cstdint>

typedef unsigned long long u64;

#define MAXN   16384
#define NCELL  512           // 8x8x8 cells of 5 Angstrom
#define CAP    128           // bucket capacity per cell (expected ~32)
#define NB_CAP 2560          // smem neighborhood capacity (float4) = 40KB
#define NBIN   4096          // histogram bins = top 12 bits of ordered key
#define CAND   2048          // candidate buffer for final sort

// ---------------- scratch (device globals, zero-initialized at load) --------
__device__ float  g_mind[MAXN];
__device__ int    g_counts[MAXN];          // only far atoms' entries read
__device__ int    g_cellcnt[NCELL];        // reset in k_scorehist each run
__device__ float4 g_bucket[NCELL * CAP];
__device__ int    g_bucketidx[NCELL * CAP];
__device__ int    g_maxcount;              // reset in k_threshcompact each run
__device__ u64    g_keys[MAXN];
__device__ int    g_hist[NBIN];            // reset in k_threshcompact each run
__device__ u64    g_cand[CAND];            // fully rewritten each run

__constant__ float c_bond[20] = {
    1.05f, 1.3f, 1.1f, 1.2f, 1.0f, 1.1f, 1.2f, 1.0f, 1.4f, 1.0f,
    1.0f,  1.3f, 1.0f, 1.5f, 1.0f, 1.05f, 1.05f, 1.6f, 1.4f, 1.1f
};

// ---------------- k1: min dist to ligand + direct bucket scatter -------------
__global__ void k_mind(const float* __restrict__ pos,
                       const float* __restrict__ lig,
                       int N, int M) {
    __shared__ float s_lig[3 * 256];
    for (int t = threadIdx.x; t < M * 3; t += blockDim.x) s_lig[t] = lig[t];
    __syncthreads();

    int i = blockIdx.x * blockDim.x + threadIdx.x;
    if (i >= N) return;

    float px = pos[3 * i + 0], py = pos[3 * i + 1], pz = pos[3 * i + 2];
    float best = 3.4e38f;
    for (int m = 0; m < M; m++) {
        float dx = px - s_lig[3 * m + 0];
        float dy = py - s_lig[3 * m + 1];
        float dz = pz - s_lig[3 * m + 2];
        best = fminf(best, dx * dx + dy * dy + dz * dz);
    }
    float d = sqrtf(fmaxf(best, 1e-12f));
    g_mind[i] = d;

    if (d > 8.0f) {
        int cx = min((int)(px * 0.2f), 7);
        int cy = min((int)(py * 0.2f), 7);
        int cz = min((int)(pz * 0.2f), 7);
        int c  = (cz << 6) | (cy << 3) | cx;
        int r  = atomicAdd(&g_cellcnt[c], 1);
        if (r < CAP) {
            g_bucket[c * CAP + r]    = make_float4(px, py, pz, 0.0f);
            g_bucketidx[c * CAP + r] = i;
        }
    }
}

// ---------------- k2: per-cell neighbor counts (27-cell smem gather) ---------
__global__ void __launch_bounds__(256) k_counts() {
    __shared__ float4 s_nb[NB_CAP];

    int c = blockIdx.x;
    int A = min(g_cellcnt[c], CAP);
    if (A == 0) return;

    int cx = c & 7, cy = (c >> 3) & 7, cz = c >> 6;

    int T = 0, T0 = 0;
    for (int dz = -1; dz <= 1; dz++) {
        int z = cz + dz; if (z < 0 || z > 7) continue;
        for (int dy = -1; dy <= 1; dy++) {
            int y = cy + dy; if (y < 0 || y > 7) continue;
            for (int dx = -1; dx <= 1; dx++) {
                int x = cx + dx; if (x < 0 || x > 7) continue;
                int nc  = (z << 6) | (y << 3) | x;
                int len = min(g_cellcnt[nc], CAP);
                if (T + len > NB_CAP) len = NB_CAP - T;  // safety clamp
                if (nc == c) T0 = T;
                for (int k = threadIdx.x; k < len; k += blockDim.x)
                    s_nb[T + k] = g_bucket[nc * CAP + k];
                T += len;
            }
        }
    }
    __syncthreads();

    int warp = threadIdx.x >> 5, lane = threadIdx.x & 31;
    int nwarps = blockDim.x >> 5;
    int wmax = 0;
    for (int a = warp; a < A; a += nwarps) {
        float4 p = s_nb[T0 + a];
        int cnt = 0;
        for (int j = lane; j < T; j += 32) {
            float4 q = s_nb[j];
            float dx = p.x - q.x, dy = p.y - q.y, dz = p.z - q.z;
            float d2 = dx * dx + dy * dy + dz * dz;
            cnt += (d2 < 25.0f && d2 > 0.0f) ? 1 : 0;
        }
        #pragma unroll
        for (int o = 16; o > 0; o >>= 1)
            cnt += __shfl_down_sync(0xffffffffu, cnt, o);
        if (lane == 0) {
            g_counts[g_bucketidx[c * CAP + a]] = cnt;
            wmax = max(wmax, cnt);
        }
    }
    if (lane == 0 && wmax > 0) atomicMax(&g_maxcount, wmax);
}

// ---------------- k3: score + key + 4096-bin histogram ------------------------
__global__ void k_scorehist(const float* __restrict__ x,
                            float* __restrict__ out, int N, int F) {
    int i = blockIdx.x * blockDim.x + threadIdx.x;

    // self-clean cell counters (k_counts already consumed them)
    if (blockIdx.x == 0) {
        for (int q = threadIdx.x; q < NCELL; q += blockDim.x) g_cellcnt[q] = 0;
    }
    if (i >= N) return;

    float d = g_mind[i];
    float sc;
    if (d <= 3.5f) {
        sc = 10.0f;
    } else if (d <= 8.0f) {
        sc = 5.0f * (8.0f - d) / 8.0f;
    } else {
        float mx = (float)g_maxcount;
        mx = (mx > 0.0f) ? mx : 1.0f;
        sc = 1.0f - (float)g_counts[i] / (mx + 1e-6f);
    }
    int rt = (int)x[i * F + 1];
    rt = min(max(rt, 0), 19);
    sc *= c_bond[rt];

    out[i] = sc;

    unsigned int b = __float_as_uint(sc);
    unsigned int u = b ^ ((b >> 31) ? 0xFFFFFFFFu : 0x80000000u);  // order-preserving
    u64 key = ((u64)u << 32) | (u64)(0xFFFFFFFFu - (unsigned)i);
    g_keys[i] = key;
    atomicAdd(&g_hist[(int)(key >> 52)], 1);
}

// ---------------- k4: suffix scan + threshold + compact (1 block) ------------
__global__ void __launch_bounds__(1024) k_threshcompact(int N, int K) {
    __shared__ int h[NBIN];          // 16KB; becomes suffix array
    __shared__ int warpsum[32];
    __shared__ int warpsuf[32];
    __shared__ int s_thr, sA, sB;

    int t = threadIdx.x, lane = t & 31, w = t >> 5;

    // load 4 bins per thread, self-clean global hist
    int b0 = g_hist[4 * t + 0]; g_hist[4 * t + 0] = 0;
    int b1 = g_hist[4 * t + 1]; g_hist[4 * t + 1] = 0;
    int b2 = g_hist[4 * t + 2]; g_hist[4 * t + 2] = 0;
    int b3 = g_hist[4 * t + 3]; g_hist[4 * t + 3] = 0;
    int local = b0 + b1 + b2 + b3;

    // inclusive suffix over lanes within warp (sum of lanes [lane..31])
    int v = local;
    #pragma unroll
    for (int off = 1; off < 32; off <<= 1) {
        int u2 = __shfl_down_sync(0xffffffffu, v, off);
        if (lane + off < 32) v += u2;
    }
    if (lane == 0) warpsum[w] = v;          // warp total
    if (t == 0) { s_thr = 0; sA = 0; sB = 0; g_maxcount = 0; }
    __syncthreads();

    if (w == 0) {
        int s = warpsum[lane];
        #pragma unroll
        for (int off = 1; off < 32; off <<= 1) {
            int u2 = __shfl_down_sync(0xffffffffu, s, off);
            if (lane + off < 32) s += u2;
        }
        warpsuf[lane] = s - warpsum[lane];  // exclusive suffix of warp totals
    }
    __syncthreads();

    // suffix values for this thread's 4 bins
    int after = (v - local) + warpsuf[w];   // sum of all bins >= 4*(t+1)
    int s3 = after + b3;
    int s2 = s3 + b2;
    int s1 = s2 + b1;
    int s0 = s1 + b0;
    h[4 * t + 0] = s0; h[4 * t + 1] = s1; h[4 * t + 2] = s2; h[4 * t + 3] = s3;
    __syncthreads();

    // threshold: largest bin with suffix >= K (suffix non-increasing)
    #pragma unroll
    for (int q = 0; q < 4; q++) {
        int i = 4 * t + q;
        int hb = h[i];
        int hn = (i + 1 < NBIN) ? h[i + 1] : 0;
        if (hb >= K && hn < K) s_thr = i;
    }
    __syncthreads();
    int Bt    = s_thr;
    int C1    = (Bt + 1 < NBIN) ? h[Bt + 1] : 0;   // count in bins > Bt (< K)
    int total = min(h[Bt], CAND);                   // all candidates

    // two-tier compaction: bins > Bt to [0, C1), bin == Bt to [C1, ...)
    for (int i = t; i < N; i += 1024) {
        u64 key = g_keys[i];
        int bin = (int)(key >> 52);
        if (bin >= Bt) {
            int p = (bin > Bt) ? atomicAdd(&sA, 1) : (C1 + atomicAdd(&sB, 1));
            if (p < CAND) g_cand[p] = key;
        }
    }
    __syncthreads();
    // pad (real keys have MSB set, 0 sorts last)
    for (int i = total + t; i < CAND; i += 1024) g_cand[i] = 0ULL;
}

// ---------------- k5: 4 parallel descending 512-sorts of candidates ----------
__global__ void __launch_bounds__(512) k_sortc() {
    __shared__ u64 s[512];
    int t = threadIdx.x;
    s[t] = g_cand[blockIdx.x * 512 + t];
    __syncthreads();

    for (int k = 2; k <= 512; k <<= 1) {
        for (int j = k >> 1; j > 0; j >>= 1) {
            int ixj = t ^ j;
            if (ixj > t) {
                u64 a = s[t], c = s[ixj];
                bool descRegion = ((t & k) == 0);
                if (descRegion ? (a < c) : (a > c)) { s[t] = c; s[ixj] = a; }
            }
            __syncthreads();
        }
    }
    g_cand[blockIdx.x * 512 + t] = s[t];
}

// ---------------- k6: merge 4 runs -> top 512, unpack + write ----------------
__global__ void __launch_bounds__(1024) k_final(float* __restrict__ out,
                                                int N, int K) {
    __shared__ u64 s[2048];
    int t = threadIdx.x;
    int half = t >> 9;          // 0 or 1
    int w = t & 511;

    // half h merges runs (2h), (2h+1); second run reversed -> bitonic
    s[half * 1024 + w]       = g_cand[(2 * half) * 512 + w];
    s[half * 1024 + 512 + w] = g_cand[(2 * half + 1) * 512 + (511 - w)];
    __syncthreads();

    // phase 1: two independent 1024-element bitonic merges (descending)
    for (int j = 512; j > 0; j >>= 1) {
        int i = half * 1024 + (((w & ~(j - 1)) << 1) | (w & (j - 1)));
        int p = i | j;
        u64 a = s[i], c = s[p];
        if (a < c) { s[i] = c; s[p] = a; }
        __syncthreads();
    }

    // phase 2: merge the two top-512s
    u64 v = 0ULL;
    if (half == 1) v = s[1024 + (511 - w)];
    __syncthreads();
    if (half == 1) s[512 + w] = v;
    __syncthreads();

    for (int j = 512; j > 0; j >>= 1) {
        if (half == 0) {
            int i = ((w & ~(j - 1)) << 1) | (w & (j - 1));
            int p = i | j;
            u64 a = s[i], c = s[p];
            if (a < c) { s[i] = c; s[p] = a; }
        }
        __syncthreads();
    }

    if (t < K) {
        u64 key = s[t];
        unsigned int u = (unsigned int)(key >> 32);
        unsigned int b = (u >> 31) ? (u ^ 0x80000000u) : (~u);
        float sc = __uint_as_float(b);
        unsigned int idx = 0xFFFFFFFFu - (unsigned int)(key & 0xFFFFFFFFull);
        out[N + t]     = sc;
        out[N + K + t] = (float)idx;
    }
}

// ---------------- launch ------------------------------------------------------
extern "C" void kernel_launch(void* const* d_in, const int* in_sizes, int n_in,
                              void* d_out, int out_size) {
    const float* pos = (const float*)d_in[0];
    const float* lig = (const float*)d_in[1];
    const float* x   = (const float*)d_in[2];
    int N = in_sizes[0] / 3;          // 16384
    int M = in_sizes[1] / 3;          // 64
    int F = in_sizes[2] / N;          // 16
    int K = (out_size - N) / 2;       // 512
    float* out = (float*)d_out;

    k_mind<<<(N + 255) / 256, 256>>>(pos, lig, N, M);
    k_counts<<<NCELL, 256>>>();
    k_scorehist<<<(N + 255) / 256, 256>>>(x, out, N, F);
    k_threshcompact<<<1, 1024>>>(N, K);
    k_sortc<<<4, 512>>>();
    k_final<<<1, 1024>>>(out, N, K);
}

// round 7
// speedup vs baseline: 2.2961x; 1.1278x over previous
#include <cuda_runtime.h>
#include <cstdint>

typedef unsigned long long u64;

#define MAXN   16384
#define NCELL  512           // 8x8x8 cells of 5 Angstrom
#define CAP    128           // bucket capacity per cell (expected ~32)
#define NB_CAP 2560          // smem neighborhood capacity (float4) = 40KB
#define NBIN   4096          // histogram bins = top 12 bits of ordered key
#define CAND   2048          // candidate buffer for final sort
#define CLN    8             // cluster size for k_select

// ---------------- scratch (device globals, zero-initialized at load) --------
__device__ float  g_mind[MAXN];
__device__ int    g_counts[MAXN];              // only far atoms' entries read
__device__ int    g_cellcnt[NCELL];            // reset in k_scorehist each run
__device__ float4 g_bucket[NCELL * CAP];
__device__ int    g_bucketidx[NCELL * CAP];
__device__ int    g_maxcount;                  // reset in k_select each run
__device__ u64    g_keys[MAXN];
__device__ __align__(16) int g_hist[NBIN];     // reset in k_select each run
__device__ u64    g_cand[CAND];
__device__ int    g_sA, g_sB;                  // compaction counters, reset in k_select

__constant__ float c_bond[20] = {
    1.05f, 1.3f, 1.1f, 1.2f, 1.0f, 1.1f, 1.2f, 1.0f, 1.4f, 1.0f,
    1.0f,  1.3f, 1.0f, 1.5f, 1.0f, 1.05f, 1.05f, 1.6f, 1.4f, 1.1f
};

// ---------------- cluster sync (global-memory producer/consumer safe) --------
__device__ __forceinline__ void cluster_sync_gl() {
    __syncthreads();
    __threadfence();
    asm volatile("barrier.cluster.arrive.aligned;" ::: "memory");
    asm volatile("barrier.cluster.wait.aligned;"   ::: "memory");
    __threadfence();
}

// ---------------- k1: min dist to ligand + direct bucket scatter -------------
__global__ void k_mind(const float* __restrict__ pos,
                       const float* __restrict__ lig,
                       int N, int M) {
    __shared__ float s_lig[3 * 256];
    for (int t = threadIdx.x; t < M * 3; t += blockDim.x) s_lig[t] = lig[t];
    __syncthreads();

    int i = blockIdx.x * blockDim.x + threadIdx.x;
    if (i >= N) return;

    float px = pos[3 * i + 0], py = pos[3 * i + 1], pz = pos[3 * i + 2];
    float best = 3.4e38f;
    for (int m = 0; m < M; m++) {
        float dx = px - s_lig[3 * m + 0];
        float dy = py - s_lig[3 * m + 1];
        float dz = pz - s_lig[3 * m + 2];
        best = fminf(best, dx * dx + dy * dy + dz * dz);
    }
    float d = sqrtf(fmaxf(best, 1e-12f));
    g_mind[i] = d;

    if (d > 8.0f) {
        int cx = min((int)(px * 0.2f), 7);
        int cy = min((int)(py * 0.2f), 7);
        int cz = min((int)(pz * 0.2f), 7);
        int c  = (cz << 6) | (cy << 3) | cx;
        int r  = atomicAdd(&g_cellcnt[c], 1);
        if (r < CAP) {
            g_bucket[c * CAP + r]    = make_float4(px, py, pz, 0.0f);
            g_bucketidx[c * CAP + r] = i;
        }
    }
}

// ---------------- k2: per-cell neighbor counts (27-cell smem gather) ---------
__global__ void __launch_bounds__(256) k_counts() {
    __shared__ float4 s_nb[NB_CAP];

    int c = blockIdx.x;
    int A = min(g_cellcnt[c], CAP);
    if (A == 0) return;

    int cx = c & 7, cy = (c >> 3) & 7, cz = c >> 6;

    int T = 0, T0 = 0;
    for (int dz = -1; dz <= 1; dz++) {
        int z = cz + dz; if (z < 0 || z > 7) continue;
        for (int dy = -1; dy <= 1; dy++) {
            int y = cy + dy; if (y < 0 || y > 7) continue;
            for (int dx = -1; dx <= 1; dx++) {
                int x = cx + dx; if (x < 0 || x > 7) continue;
                int nc  = (z << 6) | (y << 3) | x;
                int len = min(g_cellcnt[nc], CAP);
                if (T + len > NB_CAP) len = NB_CAP - T;  // safety clamp
                if (nc == c) T0 = T;
                for (int k = threadIdx.x; k < len; k += blockDim.x)
                    s_nb[T + k] = g_bucket[nc * CAP + k];
                T += len;
            }
        }
    }
    __syncthreads();

    int warp = threadIdx.x >> 5, lane = threadIdx.x & 31;
    int nwarps = blockDim.x >> 5;
    int wmax = 0;
    for (int a = warp; a < A; a += nwarps) {
        float4 p = s_nb[T0 + a];
        int cnt = 0;
        for (int j = lane; j < T; j += 32) {
            float4 q = s_nb[j];
            float dx = p.x - q.x, dy = p.y - q.y, dz = p.z - q.z;
            float d2 = dx * dx + dy * dy + dz * dz;
            cnt += (d2 < 25.0f && d2 > 0.0f) ? 1 : 0;
        }
        #pragma unroll
        for (int o = 16; o > 0; o >>= 1)
            cnt += __shfl_down_sync(0xffffffffu, cnt, o);
        if (lane == 0) {
            g_counts[g_bucketidx[c * CAP + a]] = cnt;
            wmax = max(wmax, cnt);
        }
    }
    if (lane == 0 && wmax > 0) atomicMax(&g_maxcount, wmax);
}

// ---------------- k3: score + key + 4096-bin histogram ------------------------
__global__ void k_scorehist(const float* __restrict__ x,
                            float* __restrict__ out, int N, int F) {
    int i = blockIdx.x * blockDim.x + threadIdx.x;

    // self-clean cell counters (k_counts already consumed them)
    if (blockIdx.x == 0) {
        for (int q = threadIdx.x; q < NCELL; q += blockDim.x) g_cellcnt[q] = 0;
    }
    if (i >= N) return;

    float d = g_mind[i];
    float sc;
    if (d <= 3.5f) {
        sc = 10.0f;
    } else if (d <= 8.0f) {
        sc = 5.0f * (8.0f - d) / 8.0f;
    } else {
        float mx = (float)g_maxcount;
        mx = (mx > 0.0f) ? mx : 1.0f;
        sc = 1.0f - (float)g_counts[i] / (mx + 1e-6f);
    }
    int rt = (int)x[i * F + 1];
    rt = min(max(rt, 0), 19);
    sc *= c_bond[rt];

    out[i] = sc;

    unsigned int b = __float_as_uint(sc);
    unsigned int u = b ^ ((b >> 31) ? 0xFFFFFFFFu : 0x80000000u);  // order-preserving
    u64 key = ((u64)u << 32) | (u64)(0xFFFFFFFFu - (unsigned)i);
    g_keys[i] = key;
    atomicAdd(&g_hist[(int)(key >> 52)], 1);
}

// ---------------- helper: merge two descending 512-runs, keep top 512 --------
__device__ __forceinline__ void merge2_cand(int ca, int cb, int cdst, u64* s) {
    int t = threadIdx.x;
    s[t]       = g_cand[ca * 512 + t];
    s[512 + t] = g_cand[cb * 512 + (511 - t)];   // reversed -> bitonic
    __syncthreads();
    for (int j = 512; j > 0; j >>= 1) {
        int i = ((t & ~(j - 1)) << 1) | (t & (j - 1));
        int p = i | j;
        u64 a = s[i], c = s[p];
        if (a < c) { s[i] = c; s[p] = a; }
        __syncthreads();
    }
    g_cand[cdst * 512 + t] = s[t];
}

// ---------------- k4: cluster-fused threshold/compact/sort/merge/write -------
__global__ void __cluster_dims__(CLN, 1, 1) __launch_bounds__(512)
k_select(float* __restrict__ out, int N, int K) {
    __shared__ int sh_h[NBIN];                 // 16KB; aliased as u64[2048] later
    u64* sh_k = (u64*)sh_h;
    __shared__ int warpsum[16], warpsuf[16];
    __shared__ int s_thr;

    int t = threadIdx.x, lane = t & 31, w = t >> 5;
    int blk = blockIdx.x;                      // == cluster rank (grid = 1 cluster)

    // ===== Phase 1: redundant threshold computation (all CTAs) =====
    if (t == 0) s_thr = 0;
    const int4* h4 = (const int4*)g_hist;
    int4 v0 = h4[2 * t], v1 = h4[2 * t + 1];   // bins 8t .. 8t+7
    int b[8] = { v0.x, v0.y, v0.z, v0.w, v1.x, v1.y, v1.z, v1.w };
    int local = b[0] + b[1] + b[2] + b[3] + b[4] + b[5] + b[6] + b[7];

    // warp-level inclusive suffix (sum of lanes [lane..31])
    int v = local;
    #pragma unroll
    for (int off = 1; off < 32; off <<= 1) {
        int u2 = __shfl_down_sync(0xffffffffu, v, off);
        if (lane + off < 32) v += u2;
    }
    if (lane == 0) warpsum[w] = v;
    __syncthreads();
    if (w == 0) {
        int s = (lane < 16) ? warpsum[lane] : 0;
        #pragma unroll
        for (int off = 1; off < 16; off <<= 1) {
            int u2 = __shfl_down_sync(0xffffffffu, s, off);
            if (lane + off < 16) s += u2;
        }
        if (lane < 16) warpsuf[lane] = s - warpsum[lane];  // exclusive suffix
    }
    __syncthreads();

    int after = (v - local) + warpsuf[w];      // sum of bins >= 8*(t+1)
    int suf[8];
    suf[7] = after + b[7];
    #pragma unroll
    for (int q = 6; q >= 0; q--) suf[q] = suf[q + 1] + b[q];
    #pragma unroll
    for (int q = 0; q < 8; q++) sh_h[8 * t + q] = suf[q];
    __syncthreads();

    #pragma unroll
    for (int q = 0; q < 8; q++) {
        int i = 8 * t + q;
        int hb = sh_h[i];
        int hn = (i + 1 < NBIN) ? sh_h[i + 1] : 0;
        if (hb >= K && hn < K) s_thr = i;      // exactly one bin matches
    }
    __syncthreads();
    int Bt    = s_thr;
    int C1    = (Bt + 1 < NBIN) ? sh_h[Bt + 1] : 0;  // keys in bins > Bt (< K)
    int total = min(sh_h[Bt], CAND);
    __syncthreads();                            // sh_h reads done before alias reuse

    // ===== Phase 2: parallel two-tier compaction (each CTA: N/CLN keys) =====
    int slice = N / CLN;                        // 2048
    int base  = blk * slice;
    for (int i = t; i < slice; i += 512) {
        u64 key = g_keys[base + i];
        int bin = (int)(key >> 52);
        if (bin >= Bt) {
            int p = (bin > Bt) ? atomicAdd(&g_sA, 1) : (C1 + atomicAdd(&g_sB, 1));
            if (p < CAND) g_cand[p] = key;
        }
    }
    cluster_sync_gl();

    // ===== Phase 3: CTAs 0-3 sort 512-chunks; CTAs 4-7 self-clean state =====
    if (blk < 4) {
        int idx = blk * 512 + t;
        u64 key = (idx < total) ? g_cand[idx] : 0ULL;   // pad (MSB-set keys sort first)
        sh_k[t] = key;
        __syncthreads();
        for (int k = 2; k <= 512; k <<= 1) {
            for (int j = k >> 1; j > 0; j >>= 1) {
                int ixj = t ^ j;
                if (ixj > t) {
                    u64 a = sh_k[t], c = sh_k[ixj];
                    bool descRegion = ((t & k) == 0);
                    if (descRegion ? (a < c) : (a > c)) { sh_k[t] = c; sh_k[ixj] = a; }
                }
                __syncthreads();
            }
        }
        g_cand[idx] = sh_k[t];
    } else {
        int o = (blk - 4) * 1024;
        g_hist[o + t]       = 0;                // clean 4096 hist entries across 4 CTAs
        g_hist[o + 512 + t] = 0;
        if (blk == 4 && t == 0) { g_maxcount = 0; g_sA = 0; g_sB = 0; }
    }
    cluster_sync_gl();

    // ===== Phase 4: CTAs 0,1 merge chunk pairs =====
    if (blk == 0) merge2_cand(0, 1, 0, sh_k);
    if (blk == 1) merge2_cand(2, 3, 2, sh_k);
    cluster_sync_gl();

    // ===== Phase 5: CTA 0 final merge + unpack/write top-K =====
    if (blk == 0) {
        sh_k[t]       = g_cand[t];
        sh_k[512 + t] = g_cand[2 * 512 + (511 - t)];
        __syncthreads();
        for (int j = 512; j > 0; j >>= 1) {
            int i = ((t & ~(j - 1)) << 1) | (t & (j - 1));
            int p = i | j;
            u64 a = sh_k[i], c = sh_k[p];
            if (a < c) { sh_k[i] = c; sh_k[p] = a; }
            __syncthreads();
        }
        if (t < K) {
            u64 key = sh_k[t];
            unsigned int u = (unsigned int)(key >> 32);
            unsigned int bb = (u >> 31) ? (u ^ 0x80000000u) : (~u);
            float sc = __uint_as_float(bb);
            unsigned int idx = 0xFFFFFFFFu - (unsigned int)(key & 0xFFFFFFFFull);
            out[N + t]     = sc;
            out[N + K + t] = (float)idx;
        }
    }
}

// ---------------- launch ------------------------------------------------------
extern "C" void kernel_launch(void* const* d_in, const int* in_sizes, int n_in,
                              void* d_out, int out_size) {
    const float* pos = (const float*)d_in[0];
    const float* lig = (const float*)d_in[1];
    const float* x   = (const float*)d_in[2];
    int N = in_sizes[0] / 3;          // 16384
    int M = in_sizes[1] / 3;          // 64
    int F = in_sizes[2] / N;          // 16
    int K = (out_size - N) / 2;       // 512
    float* out = (float*)d_out;

    k_mind<<<(N + 255) / 256, 256>>>(pos, lig, N, M);
    k_counts<<<NCELL, 256>>>();
    k_scorehist<<<(N + 255) / 256, 256>>>(x, out, N, F);
    k_select<<<CLN, 512>>>(out, N, K);
}

// round 8
// speedup vs baseline: 2.5390x; 1.1058x over previous
#include <cuda_runtime.h>
#include <cstdint>

typedef unsigned long long u64;

#define MAXN   16384
#define NCELL  512           // 8x8x8 cells of 5 Angstrom
#define CAP    128           // bucket capacity per cell (expected ~32)
#define NB_CAP 2560          // smem neighborhood capacity (float4) = 40KB
#define NBIN   4096          // histogram bins = top 12 bits of ordered key
#define CAND   2048          // candidate buffer for final sort
#define CLN    8             // cluster size for k_select

// ---------------- scratch (device globals, zero-initialized at load) --------
__device__ float  g_mind[MAXN];
__device__ int    g_counts[MAXN];              // only far atoms' entries read
__device__ int    g_cellcnt[NCELL];            // reset in k_select each run
__device__ float4 g_bucket[NCELL * CAP];
__device__ int    g_bucketidx[NCELL * CAP];
__device__ int    g_maxcount;                  // reset in k_select each run
__device__ __align__(16) int g_hist[NBIN];     // reset in k_select each run
__device__ u64    g_cand[CAND];
__device__ int    g_sA, g_sB;                  // compaction counters, reset in k_select

__constant__ float c_bond[20] = {
    1.05f, 1.3f, 1.1f, 1.2f, 1.0f, 1.1f, 1.2f, 1.0f, 1.4f, 1.0f,
    1.0f,  1.3f, 1.0f, 1.5f, 1.0f, 1.05f, 1.05f, 1.6f, 1.4f, 1.1f
};

// ---------------- cluster sync (global-memory producer/consumer safe) --------
__device__ __forceinline__ void cluster_sync_gl() {
    __syncthreads();
    __threadfence();
    asm volatile("barrier.cluster.arrive.aligned;" ::: "memory");
    asm volatile("barrier.cluster.wait.aligned;"   ::: "memory");
    __threadfence();
}

__device__ __forceinline__ u64 umax64(u64 a, u64 b) { return a > b ? a : b; }
__device__ __forceinline__ u64 umin64(u64 a, u64 b) { return a < b ? a : b; }

// one bitonic compare-exchange via warp shuffle (j <= 16), element in register
__device__ __forceinline__ void cas_shfl(u64& v, int j, bool desc, int t) {
    u64 u = __shfl_xor_sync(0xffffffffu, v, j);
    bool keepmax = (((t & j) == 0) == desc);
    v = keepmax ? umax64(v, u) : umin64(v, u);
}

// one bitonic compare-exchange via smem (j >= 32), element in register
__device__ __forceinline__ void cas_smem(u64& v, u64* s, int j, bool desc, int t) {
    s[t] = v;
    __syncthreads();
    u64 u = s[t ^ j];
    bool keepmax = (((t & j) == 0) == desc);
    v = keepmax ? umax64(v, u) : umin64(v, u);
    __syncthreads();
}

// full descending bitonic sort of 512 elements, thread t owns v
__device__ __forceinline__ void bitonic512_desc(u64& v, u64* s, int t) {
    // k = 2..32: fully intra-warp
    #pragma unroll
    for (int k = 2; k <= 32; k <<= 1) {
        bool desc = ((t & k) == 0);
        #pragma unroll
        for (int j = k >> 1; j > 0; j >>= 1) cas_shfl(v, j, desc, t);
    }
    // k = 64..512: smem rounds for j>=32, shfl for j<=16
    #pragma unroll
    for (int k = 64; k <= 512; k <<= 1) {
        bool desc = ((t & k) == 0);
        for (int j = k >> 1; j >= 32; j >>= 1) cas_smem(v, s, j, desc, t);
        #pragma unroll
        for (int j = 16; j > 0; j >>= 1) cas_shfl(v, j, desc, t);
    }
}

// descending bitonic MERGE of 512 elements (input bitonic), thread t owns v
__device__ __forceinline__ void bimerge512_desc(u64& v, u64* s, int t) {
    for (int j = 256; j >= 32; j >>= 1) cas_smem(v, s, j, true, t);
    #pragma unroll
    for (int j = 16; j > 0; j >>= 1) cas_shfl(v, j, true, t);
}

// ---------------- k1: min dist to ligand + direct bucket scatter -------------
__global__ void k_mind(const float* __restrict__ pos,
                       const float* __restrict__ lig,
                       int N, int M) {
    __shared__ float s_lig[3 * 256];
    for (int t = threadIdx.x; t < M * 3; t += blockDim.x) s_lig[t] = lig[t];
    __syncthreads();

    int i = blockIdx.x * blockDim.x + threadIdx.x;
    if (i >= N) return;

    float px = pos[3 * i + 0], py = pos[3 * i + 1], pz = pos[3 * i + 2];
    float best = 3.4e38f;
    for (int m = 0; m < M; m++) {
        float dx = px - s_lig[3 * m + 0];
        float dy = py - s_lig[3 * m + 1];
        float dz = pz - s_lig[3 * m + 2];
        best = fminf(best, dx * dx + dy * dy + dz * dz);
    }
    float d = sqrtf(fmaxf(best, 1e-12f));
    g_mind[i] = d;

    if (d > 8.0f) {
        int cx = min((int)(px * 0.2f), 7);
        int cy = min((int)(py * 0.2f), 7);
        int cz = min((int)(pz * 0.2f), 7);
        int c  = (cz << 6) | (cy << 3) | cx;
        int r  = atomicAdd(&g_cellcnt[c], 1);
        if (r < CAP) {
            g_bucket[c * CAP + r]    = make_float4(px, py, pz, 0.0f);
            g_bucketidx[c * CAP + r] = i;
        }
    }
}

// ---------------- k2: per-cell neighbor counts (27-cell smem gather) ---------
__global__ void __launch_bounds__(256) k_counts() {
    __shared__ float4 s_nb[NB_CAP];

    int c = blockIdx.x;
    int A = min(g_cellcnt[c], CAP);
    if (A == 0) return;

    int cx = c & 7, cy = (c >> 3) & 7, cz = c >> 6;

    int T = 0, T0 = 0;
    for (int dz = -1; dz <= 1; dz++) {
        int z = cz + dz; if (z < 0 || z > 7) continue;
        for (int dy = -1; dy <= 1; dy++) {
            int y = cy + dy; if (y < 0 || y > 7) continue;
            for (int dx = -1; dx <= 1; dx++) {
                int x = cx + dx; if (x < 0 || x > 7) continue;
                int nc  = (z << 6) | (y << 3) | x;
                int len = min(g_cellcnt[nc], CAP);
                if (T + len > NB_CAP) len = NB_CAP - T;  // safety clamp
                if (nc == c) T0 = T;
                for (int k = threadIdx.x; k < len; k += blockDim.x)
                    s_nb[T + k] = g_bucket[nc * CAP + k];
                T += len;
            }
        }
    }
    __syncthreads();

    int warp = threadIdx.x >> 5, lane = threadIdx.x & 31;
    int nwarps = blockDim.x >> 5;
    int wmax = 0;
    for (int a = warp; a < A; a += nwarps) {
        float4 p = s_nb[T0 + a];
        int cnt = 0;
        for (int j = lane; j < T; j += 32) {
            float4 q = s_nb[j];
            float dx = p.x - q.x, dy = p.y - q.y, dz = p.z - q.z;
            float d2 = dx * dx + dy * dy + dz * dz;
            cnt += (d2 < 25.0f && d2 > 0.0f) ? 1 : 0;
        }
        #pragma unroll
        for (int o = 16; o > 0; o >>= 1)
            cnt += __shfl_down_sync(0xffffffffu, cnt, o);
        if (lane == 0) {
            g_counts[g_bucketidx[c * CAP + a]] = cnt;
            wmax = max(wmax, cnt);
        }
    }
    if (lane == 0 && wmax > 0) atomicMax(&g_maxcount, wmax);
}

// ---------------- k3: fused score/hist/threshold/compact/sort/merge/write ----
__global__ void __cluster_dims__(CLN, 1, 1) __launch_bounds__(512)
k_select(const float* __restrict__ x, float* __restrict__ out,
         int N, int F, int K) {
    __shared__ u64 sh_u64[NBIN / 2];           // 16KB; int[4096] alias for hist scan
    int* sh_h = (int*)sh_u64;
    __shared__ int warpsum[16], warpsuf[16];
    __shared__ int s_thr;

    int t = threadIdx.x, lane = t & 31, w = t >> 5;
    int blk = blockIdx.x;                      // == cluster rank (grid = 1 cluster)

    // ===== Phase 0: scores + keys (registers) + global histogram =====
    int slice = N / CLN;                       // 2048
    int base  = blk * slice;
    float mx  = (float)g_maxcount;
    mx = (mx > 0.0f) ? mx : 1.0f;
    float inv_mx = 1.0f / (mx + 1e-6f);

    u64 keys[4];
    #pragma unroll
    for (int q = 0; q < 4; q++) {
        int i = base + q * 512 + t;
        float d = g_mind[i];
        float sc;
        if (d <= 3.5f) {
            sc = 10.0f;
        } else if (d <= 8.0f) {
            sc = 5.0f * (8.0f - d) / 8.0f;
        } else {
            sc = 1.0f - (float)g_counts[i] * inv_mx;
        }
        int rt = (int)x[i * F + 1];
        rt = min(max(rt, 0), 19);
        sc *= c_bond[rt];

        out[i] = sc;

        unsigned int b = __float_as_uint(sc);
        unsigned int u = b ^ ((b >> 31) ? 0xFFFFFFFFu : 0x80000000u);
        keys[q] = ((u64)u << 32) | (u64)(0xFFFFFFFFu - (unsigned)i);
        atomicAdd(&g_hist[(int)(keys[q] >> 52)], 1);
    }
    cluster_sync_gl();

    // ===== Phase 1: redundant threshold computation (all CTAs) =====
    if (t == 0) s_thr = 0;
    const int4* h4 = (const int4*)g_hist;
    int4 v0 = h4[2 * t], v1 = h4[2 * t + 1];   // bins 8t .. 8t+7
    int b8[8] = { v0.x, v0.y, v0.z, v0.w, v1.x, v1.y, v1.z, v1.w };
    int local = b8[0] + b8[1] + b8[2] + b8[3] + b8[4] + b8[5] + b8[6] + b8[7];

    int v = local;
    #pragma unroll
    for (int off = 1; off < 32; off <<= 1) {
        int u2 = __shfl_down_sync(0xffffffffu, v, off);
        if (lane + off < 32) v += u2;
    }
    if (lane == 0) warpsum[w] = v;
    __syncthreads();
    if (w == 0) {
        int s = (lane < 16) ? warpsum[lane] : 0;
        #pragma unroll
        for (int off = 1; off < 16; off <<= 1) {
            int u2 = __shfl_down_sync(0xffffffffu, s, off);
            if (lane + off < 16) s += u2;
        }
        if (lane < 16) warpsuf[lane] = s - warpsum[lane];  // exclusive suffix
    }
    __syncthreads();

    int after = (v - local) + warpsuf[w];      // sum of bins >= 8*(t+1)
    int suf[8];
    suf[7] = after + b8[7];
    #pragma unroll
    for (int q = 6; q >= 0; q--) suf[q] = suf[q + 1] + b8[q];
    #pragma unroll
    for (int q = 0; q < 8; q++) sh_h[8 * t + q] = suf[q];
    __syncthreads();

    #pragma unroll
    for (int q = 0; q < 8; q++) {
        int i = 8 * t + q;
        int hb = sh_h[i];
        int hn = (i + 1 < NBIN) ? sh_h[i + 1] : 0;
        if (hb >= K && hn < K) s_thr = i;      // exactly one bin matches
    }
    __syncthreads();
    int Bt    = s_thr;
    int C1    = (Bt + 1 < NBIN) ? sh_h[Bt + 1] : 0;  // keys in bins > Bt (< K)
    int total = min(sh_h[Bt], CAND);
    __syncthreads();                            // sh_h done before smem reuse

    // ===== Phase 2: two-tier compaction straight from registers =====
    #pragma unroll
    for (int q = 0; q < 4; q++) {
        int bin = (int)(keys[q] >> 52);
        if (bin >= Bt) {
            int p = (bin > Bt) ? atomicAdd(&g_sA, 1) : (C1 + atomicAdd(&g_sB, 1));
            if (p < CAND) g_cand[p] = keys[q];
        }
    }
    cluster_sync_gl();

    // ===== Phase 3: CTAs 0-3 hybrid-sort 512-chunks; CTAs 4-7 clean state =====
    if (blk < 4) {
        int idx = blk * 512 + t;
        u64 vv = (idx < total) ? g_cand[idx] : 0ULL;  // pad: real keys have MSB set
        bitonic512_desc(vv, sh_u64, t);
        g_cand[idx] = vv;
    } else {
        int o = (blk - 4) * 1024;
        g_hist[o + t]       = 0;
        g_hist[o + 512 + t] = 0;
        if (blk == 4) {
            if (t < NCELL) g_cellcnt[t] = 0;
            if (t == 0) { g_maxcount = 0; g_sA = 0; g_sB = 0; }
        }
    }
    cluster_sync_gl();

    // ===== Phase 4: CTAs 0,1 merge chunk pairs (keep top 512 each) =====
    if (blk == 0) {
        u64 vv = umax64(g_cand[t], g_cand[512 + (511 - t)]);
        bimerge512_desc(vv, sh_u64, t);
        g_cand[t] = vv;
    } else if (blk == 1) {
        u64 vv = umax64(g_cand[1024 + t], g_cand[1536 + (511 - t)]);
        bimerge512_desc(vv, sh_u64, t);
        g_cand[1024 + t] = vv;
    }
    cluster_sync_gl();

    // ===== Phase 5: CTA 0 final merge + unpack/write top-K =====
    if (blk == 0) {
        u64 vv = umax64(g_cand[t], g_cand[1024 + (511 - t)]);
        bimerge512_desc(vv, sh_u64, t);
        if (t < K) {
            unsigned int u = (unsigned int)(vv >> 32);
            unsigned int bb = (u >> 31) ? (u ^ 0x80000000u) : (~u);
            float sc = __uint_as_float(bb);
            unsigned int idx = 0xFFFFFFFFu - (unsigned int)(vv & 0xFFFFFFFFull);
            out[N + t]     = sc;
            out[N + K + t] = (float)idx;
        }
    }
}

// ---------------- launch ------------------------------------------------------
extern "C" void kernel_launch(void* const* d_in, const int* in_sizes, int n_in,
                              void* d_out, int out_size) {
    const float* pos = (const float*)d_in[0];
    const float* lig = (const float*)d_in[1];
    const float* x   = (const float*)d_in[2];
    int N = in_sizes[0] / 3;          // 16384
    int M = in_sizes[1] / 3;          // 64
    int F = in_sizes[2] / N;          // 16
    int K = (out_size - N) / 2;       // 512
    float* out = (float*)d_out;

    k_mind<<<(N + 255) / 256, 256>>>(pos, lig, N, M);
    k_counts<<<NCELL, 256>>>();
    k_select<<<CLN, 512>>>(x, out, N, F, K);
}